// round 14
// baseline (speedup 1.0000x reference)
#include <cuda_runtime.h>

#define K_DIM 7168
#define E_DIM 256
#define BM 128
#define BN 32
#define BK 16
#define KC_TILES 20              // Eigen kc=320 floats = 20 tiles of BK=16
#define SMEM_BYTES (120 * 1024)  // force occupancy = 1 CTA/SM (tiles use 20KB)

// packed f32x2 FMA (Blackwell): per-component IEEE rn fma
__device__ __forceinline__ unsigned long long ffma2(unsigned long long a,
                                                    unsigned long long b,
                                                    unsigned long long c) {
    unsigned long long d;
    asm("fma.rn.f32x2 %0, %1, %2, %3;" : "=l"(d) : "l"(a), "l"(b), "l"(c));
    return d;
}

__device__ __forceinline__ unsigned long long fadd2(unsigned long long a,
                                                    unsigned long long b) {
    unsigned long long d;
    asm("add.rn.f32x2 %0, %1, %2;" : "=l"(d) : "l"(a), "l"(b));
    return d;
}

__device__ __forceinline__ unsigned long long dup_f32(float a) {
    unsigned long long p;
    asm("mov.b64 %0, {%1, %1};" : "=l"(p) : "r"(__float_as_uint(a)));
    return p;
}

// C[t, e] = sum_k A[t,k] * W[e,k] — fp32, Eigen-blocked accumulation order:
// c = ((0 + S_0) + S_1) + ... ; S_b = ascending-k fma partial over kc=320 block
// (last block = 128). BIT-EXACT match to XLA:CPU Eigen gemm — do not reorder.
//
// BM=128 x BN=32 -> 1024 tiles; 512 threads, occupancy FORCED to 1 via 120KB
// smem request -> 16 warps/SM (R8-proven) AND 6.92 tiles/SM (98.9% drain,
// kills R8's 13.5% two-wave tail). Per thread 8m x 1n, M-PACKED accumulators:
// per warp-k only 2 broadcast LDS.128 + 1 LDS.32 + 1 dup + 4 FFMA2 = 8 instr
// vs 48-cyc FFMA2 bank window (33% issue slack). ~50 regs -> no spills.
__global__ __launch_bounds__(512)
void moe_gemm_kernel(const float* __restrict__ A,
                     const float* __restrict__ W,
                     float* __restrict__ C, int T) {
    extern __shared__ char smem_raw[];
    float (*As)[BK][BM] = reinterpret_cast<float (*)[BK][BM]>(smem_raw);
    float (*Bs)[BK][BN] =
        reinterpret_cast<float (*)[BK][BN]>(smem_raw + 2 * BK * BM * 4);

    const int tid = threadIdx.x;
    const int lane = tid & 31;   // n: 1 expert per thread (lane)
    const int wid = tid >> 5;    // m: 8 tokens per thread (16 warps x 8 = 128)
    const int n0 = blockIdx.x * BN;   // grid.x = 8 n-tiles (fast: A L2 reuse)
    const int m0 = blockIdx.y * BM;   // grid.y = 128 m-tiles

    // A loader: 4 threads per row, one float4 each (128 rows x 16 k)
    const int alr = tid >> 2;
    const int alc = (tid & 3) * 4;
    const float* Abase = A + (size_t)(m0 + alr) * K_DIM + alc;
    // B loader: threads 0..127, 4 threads per row, one float4 (32 rows x 16 k)
    const int blr = tid >> 2;          // valid when tid < 128
    const int blc = (tid & 3) * 4;
    const float* Wbase = W + (size_t)(n0 + blr) * K_DIM + blc;
    const bool bload = (tid < 128);

    // acc[p] packs tokens (m0 + wid*8 + 2p, +2p+1) for expert n0+lane
    unsigned long long acc[4], bac[4];
#pragma unroll
    for (int p = 0; p < 4; ++p) { acc[p] = 0ull; bac[p] = 0ull; }

    float4 aP = *reinterpret_cast<const float4*>(Abase);
    float4 bP;
    if (bload) bP = *reinterpret_cast<const float4*>(Wbase);

    const int nIter = K_DIM / BK;  // 448
    for (int kt = 0; kt < nIter; ++kt) {
        const int buf = kt & 1;
        As[buf][alc + 0][alr] = aP.x; As[buf][alc + 1][alr] = aP.y;
        As[buf][alc + 2][alr] = aP.z; As[buf][alc + 3][alr] = aP.w;
        if (bload) {
            Bs[buf][blc + 0][blr] = bP.x; Bs[buf][blc + 1][blr] = bP.y;
            Bs[buf][blc + 2][blr] = bP.z; Bs[buf][blc + 3][blr] = bP.w;
        }
        __syncthreads();

        // prefetch next tile from global (hidden by 16 warps/SM)
        if (kt + 1 < nIter) {
            aP = *reinterpret_cast<const float4*>(Abase + (size_t)(kt + 1) * BK);
            if (bload)
                bP = *reinterpret_cast<const float4*>(Wbase + (size_t)(kt + 1) * BK);
        }

#pragma unroll
        for (int k = 0; k < BK; ++k) {
            // A: 8 m-floats = 4 packed pairs, 2 broadcast LDS.128 (lane-invariant)
            ulonglong2 a01 = *reinterpret_cast<const ulonglong2*>(
                &As[buf][k][wid * 8]);
            ulonglong2 a23 = *reinterpret_cast<const ulonglong2*>(
                &As[buf][k][wid * 8 + 4]);
            // B: one scalar per lane, conflict-free, duplicated once
            unsigned long long pb = dup_f32(Bs[buf][k][lane]);
            bac[0] = ffma2(a01.x, pb, bac[0]);
            bac[1] = ffma2(a01.y, pb, bac[1]);
            bac[2] = ffma2(a23.x, pb, bac[2]);
            bac[3] = ffma2(a23.y, pb, bac[3]);
        }

        // Eigen kc=320 block boundary: c += S_b; S_b = 0
        if (((kt + 1) % KC_TILES) == 0) {
#pragma unroll
            for (int p = 0; p < 4; ++p) {
                acc[p] = fadd2(acc[p], bac[p]);
                bac[p] = 0ull;
            }
        }
    }

    // final (remainder 128-wide) block flush
#pragma unroll
    for (int p = 0; p < 4; ++p) acc[p] = fadd2(acc[p], bac[p]);

    // epilogue: acc[p] component c -> C[m0+wid*8+2p+c][n0+lane]
    // consecutive lanes -> consecutive n -> coalesced 128B stores per row
#pragma unroll
    for (int p = 0; p < 4; ++p) {
        float2 v = *reinterpret_cast<float2*>(&acc[p]);
        int m = m0 + wid * 8 + p * 2;
        C[(size_t)m * E_DIM + n0 + lane] = v.x;
        C[(size_t)(m + 1) * E_DIM + n0 + lane] = v.y;
    }
}

// XLA EmitFastTanh replica — UNFUSED mul/add Horner (CPU LLVM does not
// contract), IEEE fdiv, clamp +-7.90531110763549805, |x|<0.0004 -> x.
__device__ __forceinline__ float xla_tanhf_nofma(float x) {
    float xc = fminf(fmaxf(x, -7.90531110763549805f), 7.90531110763549805f);
    float x2 = __fmul_rn(xc, xc);
    float np = -2.76076847742355e-16f;
    np = __fadd_rn(__fmul_rn(x2, np),  2.00018790482477e-13f);
    np = __fadd_rn(__fmul_rn(x2, np), -8.60467152213735e-11f);
    np = __fadd_rn(__fmul_rn(x2, np),  5.12229709037114e-08f);
    np = __fadd_rn(__fmul_rn(x2, np),  1.48572235717979e-05f);
    np = __fadd_rn(__fmul_rn(x2, np),  6.37261928875436e-04f);
    np = __fadd_rn(__fmul_rn(x2, np),  4.89352455891786e-03f);
    float num = __fmul_rn(xc, np);
    float dp = 1.19825839466702e-06f;
    dp = __fadd_rn(__fmul_rn(x2, dp), 1.18534705686654e-04f);
    dp = __fadd_rn(__fmul_rn(x2, dp), 2.26843463243900e-03f);
    dp = __fadd_rn(__fmul_rn(x2, dp), 4.89352518554385e-03f);
    float r = __fdiv_rn(num, dp);
    return (fabsf(x) < 0.0004f) ? x : r;
}

// XLA logistic: 0.5 + 0.5 * tanh(0.5 * x), unfused.
__device__ __forceinline__ float sigmoid_xla(float x) {
    float t = xla_tanhf_nofma(__fmul_rn(0.5f, x));
    return __fadd_rn(0.5f, __fmul_rn(0.5f, t));
}

// one warp per token
__global__ void moe_router_kernel(const float* __restrict__ logits,
                                  float* __restrict__ outW,
                                  float* __restrict__ outI, int T) {
    const unsigned FULL = 0xFFFFFFFFu;
    int warp = (blockIdx.x * blockDim.x + threadIdx.x) >> 5;
    int lane = threadIdx.x & 31;
    if (warp >= T) return;

    const float* row = logits + (size_t)warp * E_DIM;
    float4 v0 = *reinterpret_cast<const float4*>(row + lane * 8);
    float4 v1 = *reinterpret_cast<const float4*>(row + lane * 8 + 4);

    float s[8];
    s[0] = sigmoid_xla(v0.x); s[1] = sigmoid_xla(v0.y);
    s[2] = sigmoid_xla(v0.z); s[3] = sigmoid_xla(v0.w);
    s[4] = sigmoid_xla(v1.x); s[5] = sigmoid_xla(v1.y);
    s[6] = sigmoid_xla(v1.z); s[7] = sigmoid_xla(v1.w);

    // group sum over 32 experts (butterfly tree)
    float f[8];
#pragma unroll
    for (int j = 0; j < 8; ++j)
        f[j] = s[j] + __shfl_xor_sync(FULL, s[j], 2);
    float g[8];
#pragma unroll
    for (int j = 0; j < 8; ++j)
        g[j] = f[j] + __shfl_xor_sync(FULL, f[j], 1);
    float h0 = g[0] + g[4];
    float h1 = g[1] + g[5];
    float h2 = g[2] + g[6];
    float h3 = g[3] + g[7];
    float p0 = h0 + h2;
    float p1 = h1 + h3;
    float mygs = p0 + p1;     // group sum for group (lane>>2)
    int myg = lane >> 2;

    // rank of my group among 8 groups (ties -> lower index, jax top_k)
    int rank = 0;
#pragma unroll
    for (int h = 0; h < 8; ++h) {
        float gh = __shfl_sync(FULL, mygs, h * 4);
        if (h != myg && (gh > mygs || (gh == mygs && h < myg))) rank++;
    }
    bool sel = (rank < 4);

    float ms[8];
#pragma unroll
    for (int j = 0; j < 8; ++j) ms[j] = sel ? s[j] : 0.0f;

    float topv[8];
    int topi[8];
#pragma unroll
    for (int it = 0; it < 8; ++it) {
        float bv = -1.0f;
        int bi = 0;
#pragma unroll
        for (int j = 0; j < 8; ++j) {
            if (ms[j] > bv) { bv = ms[j]; bi = lane * 8 + j; }
        }
#pragma unroll
        for (int off = 16; off; off >>= 1) {
            float ov = __shfl_xor_sync(FULL, bv, off);
            int oi = __shfl_xor_sync(FULL, bi, off);
            if (ov > bv || (ov == bv && oi < bi)) { bv = ov; bi = oi; }
        }
        topv[it] = bv;
        topi[it] = bi;
        if ((bi >> 3) == lane) ms[bi & 7] = -1.0f;
    }

    float denom = 0.f;
#pragma unroll
    for (int it = 0; it < 8; ++it) denom += topv[it];
    denom = fmaxf(denom, 1e-12f);

    if (lane < 8) {
        outW[(size_t)warp * 8 + lane] = __fdiv_rn(topv[lane], denom);
        outI[(size_t)warp * 8 + lane] = (float)topi[lane];
    }
}

extern "C" void kernel_launch(void* const* d_in, const int* in_sizes, int n_in,
                              void* d_out, int out_size) {
    const float* H = (const float*)d_in[0];   // [T, 7168] fp32
    const float* W = (const float*)d_in[1];   // [256, 7168] fp32
    float* out = (float*)d_out;

    int T = in_sizes[0] / K_DIM;

    // output layout: [T*8 weights][T*8 indices][T*256 logits]
    float* outW = out;
    float* outI = out + (size_t)T * 8;
    float* logits = out + (size_t)T * 16;

    cudaFuncSetAttribute(moe_gemm_kernel,
                         cudaFuncAttributeMaxDynamicSharedMemorySize, SMEM_BYTES);

    // n-fastest: 148 live CTAs span 18.5 m-tiles (68MB) -> A re-reads hit L2
    dim3 grid(E_DIM / BN, T / BM);
    moe_gemm_kernel<<<grid, 512, SMEM_BYTES>>>(H, W, logits, T);

    int warps = T;
    int threads = 256;
    int blocks = (warps * 32 + threads - 1) / threads;
    moe_router_kernel<<<blocks, threads>>>(logits, outW, outI, T);
}

// round 15
// speedup vs baseline: 1.4371x; 1.4371x over previous
#include <cuda_runtime.h>

#define K_DIM 7168
#define E_DIM 256
#define BM 128
#define BN 128
#define BK 16
#define KC_TILES 20   // Eigen kc=320 floats = 20 tiles of BK=16

// packed f32x2 FMA (Blackwell): per-component IEEE rn fma
__device__ __forceinline__ unsigned long long ffma2(unsigned long long a,
                                                    unsigned long long b,
                                                    unsigned long long c) {
    unsigned long long d;
    asm("fma.rn.f32x2 %0, %1, %2, %3;" : "=l"(d) : "l"(a), "l"(b), "l"(c));
    return d;
}

__device__ __forceinline__ unsigned long long fadd2(unsigned long long a,
                                                    unsigned long long b) {
    unsigned long long d;
    asm("add.rn.f32x2 %0, %1, %2;" : "=l"(d) : "l"(a), "l"(b));
    return d;
}

// C[t, e] = sum_k A[t,k] * W[e,k] — fp32, Eigen-blocked accumulation order:
// c = ((0 + S_0) + S_1) + ... ; S_b = ascending-k fma partial over kc=320 block
// (last block = 128). BIT-EXACT match to XLA:CPU Eigen gemm — do not reorder.
//
// R8 skeleton (512 threads, 128x128 tile, 8m x 4n per thread, 2 waves) with
// ONE change: A is stored PRE-DUPLICATED in smem ((v,v) pairs), eliminating
// the 8 mov.b64 dups per thread-k. Per warp-k issue: 27 -> 21 slots
// (16 FFMA2 + 4 broadcast LDS.128 for A-dup + 1 LDS.128 for B).
__global__ __launch_bounds__(512)
void moe_gemm_kernel(const float* __restrict__ A,
                     const float* __restrict__ W,
                     float* __restrict__ C, int T) {
    __shared__ float Ad[2][BK][2 * BM];   // A duplicated: (k, 2m)=(k,2m+1)=a[m][k]
    __shared__ float Bs[2][BK][BN];

    const int tid = threadIdx.x;
    const int tx = tid & 31;   // expert direction: 4 experts per thread
    const int ty = tid >> 5;   // token direction:  8 tokens per thread (warp id)
    const int m0 = blockIdx.x * BM;
    const int n0 = blockIdx.y * BN;

    // loader: 4 threads per row, one float4 each (128 rows x 16 k)
    const int lr = tid >> 2;          // row 0..127
    const int lc = (tid & 3) * 4;     // K offset 0,4,8,12

    const float* Abase = A + (size_t)(m0 + lr) * K_DIM + lc;
    const float* Wbase = W + (size_t)(n0 + lr) * K_DIM + lc;

    unsigned long long acc[8][2];   // running c (8m x 4n, n-packed)
    unsigned long long bac[8][2];   // current kc-block partial S_b
#pragma unroll
    for (int i = 0; i < 8; i++)
#pragma unroll
        for (int j = 0; j < 2; j++) { acc[i][j] = 0ull; bac[i][j] = 0ull; }

    float4 aP = *reinterpret_cast<const float4*>(Abase);
    float4 bP = *reinterpret_cast<const float4*>(Wbase);

    const int nIter = K_DIM / BK;  // 448
    for (int kt = 0; kt < nIter; ++kt) {
        const int buf = kt & 1;
        // A stored duplicated: 4 STS.64 (same count as R8's 4 STS.32)
        *reinterpret_cast<float2*>(&Ad[buf][lc + 0][2 * lr]) = make_float2(aP.x, aP.x);
        *reinterpret_cast<float2*>(&Ad[buf][lc + 1][2 * lr]) = make_float2(aP.y, aP.y);
        *reinterpret_cast<float2*>(&Ad[buf][lc + 2][2 * lr]) = make_float2(aP.z, aP.z);
        *reinterpret_cast<float2*>(&Ad[buf][lc + 3][2 * lr]) = make_float2(aP.w, aP.w);
        Bs[buf][lc + 0][lr] = bP.x; Bs[buf][lc + 1][lr] = bP.y;
        Bs[buf][lc + 2][lr] = bP.z; Bs[buf][lc + 3][lr] = bP.w;
        __syncthreads();

        // prefetch next tile from global (hidden under compute below)
        if (kt + 1 < nIter) {
            aP = *reinterpret_cast<const float4*>(Abase + (size_t)(kt + 1) * BK);
            bP = *reinterpret_cast<const float4*>(Wbase + (size_t)(kt + 1) * BK);
        }

#pragma unroll
        for (int k = 0; k < BK; ++k) {
            // A: 8 m dup-pairs = 64B, 4 broadcast LDS.128 (lane-invariant addr)
            const ulonglong2* arow =
                reinterpret_cast<const ulonglong2*>(&Ad[buf][k][ty * 16]);
            ulonglong2 q0 = arow[0];   // pa for m+0, m+1
            ulonglong2 q1 = arow[1];   // pa for m+2, m+3
            ulonglong2 q2 = arow[2];   // pa for m+4, m+5
            ulonglong2 q3 = arow[3];   // pa for m+6, m+7
            // B: 4 experts = 2 natural packed pairs, 1 LDS.128
            ulonglong2 bp = *reinterpret_cast<const ulonglong2*>(&Bs[buf][k][tx * 4]);
            bac[0][0] = ffma2(q0.x, bp.x, bac[0][0]);
            bac[0][1] = ffma2(q0.x, bp.y, bac[0][1]);
            bac[1][0] = ffma2(q0.y, bp.x, bac[1][0]);
            bac[1][1] = ffma2(q0.y, bp.y, bac[1][1]);
            bac[2][0] = ffma2(q1.x, bp.x, bac[2][0]);
            bac[2][1] = ffma2(q1.x, bp.y, bac[2][1]);
            bac[3][0] = ffma2(q1.y, bp.x, bac[3][0]);
            bac[3][1] = ffma2(q1.y, bp.y, bac[3][1]);
            bac[4][0] = ffma2(q2.x, bp.x, bac[4][0]);
            bac[4][1] = ffma2(q2.x, bp.y, bac[4][1]);
            bac[5][0] = ffma2(q2.y, bp.x, bac[5][0]);
            bac[5][1] = ffma2(q2.y, bp.y, bac[5][1]);
            bac[6][0] = ffma2(q3.x, bp.x, bac[6][0]);
            bac[6][1] = ffma2(q3.x, bp.y, bac[6][1]);
            bac[7][0] = ffma2(q3.y, bp.x, bac[7][0]);
            bac[7][1] = ffma2(q3.y, bp.y, bac[7][1]);
        }

        // Eigen kc=320 block boundary: c += S_b; S_b = 0
        if (((kt + 1) % KC_TILES) == 0) {
#pragma unroll
            for (int i = 0; i < 8; ++i)
#pragma unroll
                for (int j = 0; j < 2; ++j) {
                    acc[i][j] = fadd2(acc[i][j], bac[i][j]);
                    bac[i][j] = 0ull;
                }
        }
    }

    // final (remainder 128-wide) block flush
#pragma unroll
    for (int i = 0; i < 8; ++i)
#pragma unroll
        for (int j = 0; j < 2; ++j)
            acc[i][j] = fadd2(acc[i][j], bac[i][j]);

#pragma unroll
    for (int i = 0; i < 8; ++i) {
        int m = m0 + ty * 8 + i;
        float* crow = C + (size_t)m * E_DIM + n0 + tx * 4;
        float2 f0 = *reinterpret_cast<float2*>(&acc[i][0]);
        float2 f1 = *reinterpret_cast<float2*>(&acc[i][1]);
        *reinterpret_cast<float4*>(crow) = make_float4(f0.x, f0.y, f1.x, f1.y);
    }
}

// XLA EmitFastTanh replica — UNFUSED mul/add Horner (CPU LLVM does not
// contract), IEEE fdiv, clamp +-7.90531110763549805, |x|<0.0004 -> x.
__device__ __forceinline__ float xla_tanhf_nofma(float x) {
    float xc = fminf(fmaxf(x, -7.90531110763549805f), 7.90531110763549805f);
    float x2 = __fmul_rn(xc, xc);
    float np = -2.76076847742355e-16f;
    np = __fadd_rn(__fmul_rn(x2, np),  2.00018790482477e-13f);
    np = __fadd_rn(__fmul_rn(x2, np), -8.60467152213735e-11f);
    np = __fadd_rn(__fmul_rn(x2, np),  5.12229709037114e-08f);
    np = __fadd_rn(__fmul_rn(x2, np),  1.48572235717979e-05f);
    np = __fadd_rn(__fmul_rn(x2, np),  6.37261928875436e-04f);
    np = __fadd_rn(__fmul_rn(x2, np),  4.89352455891786e-03f);
    float num = __fmul_rn(xc, np);
    float dp = 1.19825839466702e-06f;
    dp = __fadd_rn(__fmul_rn(x2, dp), 1.18534705686654e-04f);
    dp = __fadd_rn(__fmul_rn(x2, dp), 2.26843463243900e-03f);
    dp = __fadd_rn(__fmul_rn(x2, dp), 4.89352518554385e-03f);
    float r = __fdiv_rn(num, dp);
    return (fabsf(x) < 0.0004f) ? x : r;
}

// XLA logistic: 0.5 + 0.5 * tanh(0.5 * x), unfused.
__device__ __forceinline__ float sigmoid_xla(float x) {
    float t = xla_tanhf_nofma(__fmul_rn(0.5f, x));
    return __fadd_rn(0.5f, __fmul_rn(0.5f, t));
}

// one warp per token
__global__ void moe_router_kernel(const float* __restrict__ logits,
                                  float* __restrict__ outW,
                                  float* __restrict__ outI, int T) {
    const unsigned FULL = 0xFFFFFFFFu;
    int warp = (blockIdx.x * blockDim.x + threadIdx.x) >> 5;
    int lane = threadIdx.x & 31;
    if (warp >= T) return;

    const float* row = logits + (size_t)warp * E_DIM;
    float4 v0 = *reinterpret_cast<const float4*>(row + lane * 8);
    float4 v1 = *reinterpret_cast<const float4*>(row + lane * 8 + 4);

    float s[8];
    s[0] = sigmoid_xla(v0.x); s[1] = sigmoid_xla(v0.y);
    s[2] = sigmoid_xla(v0.z); s[3] = sigmoid_xla(v0.w);
    s[4] = sigmoid_xla(v1.x); s[5] = sigmoid_xla(v1.y);
    s[6] = sigmoid_xla(v1.z); s[7] = sigmoid_xla(v1.w);

    // group sum over 32 experts (butterfly tree)
    float f[8];
#pragma unroll
    for (int j = 0; j < 8; ++j)
        f[j] = s[j] + __shfl_xor_sync(FULL, s[j], 2);
    float g[8];
#pragma unroll
    for (int j = 0; j < 8; ++j)
        g[j] = f[j] + __shfl_xor_sync(FULL, f[j], 1);
    float h0 = g[0] + g[4];
    float h1 = g[1] + g[5];
    float h2 = g[2] + g[6];
    float h3 = g[3] + g[7];
    float p0 = h0 + h2;
    float p1 = h1 + h3;
    float mygs = p0 + p1;     // group sum for group (lane>>2)
    int myg = lane >> 2;

    // rank of my group among 8 groups (ties -> lower index, jax top_k)
    int rank = 0;
#pragma unroll
    for (int h = 0; h < 8; ++h) {
        float gh = __shfl_sync(FULL, mygs, h * 4);
        if (h != myg && (gh > mygs || (gh == mygs && h < myg))) rank++;
    }
    bool sel = (rank < 4);

    float ms[8];
#pragma unroll
    for (int j = 0; j < 8; ++j) ms[j] = sel ? s[j] : 0.0f;

    float topv[8];
    int topi[8];
#pragma unroll
    for (int it = 0; it < 8; ++it) {
        float bv = -1.0f;
        int bi = 0;
#pragma unroll
        for (int j = 0; j < 8; ++j) {
            if (ms[j] > bv) { bv = ms[j]; bi = lane * 8 + j; }
        }
#pragma unroll
        for (int off = 16; off; off >>= 1) {
            float ov = __shfl_xor_sync(FULL, bv, off);
            int oi = __shfl_xor_sync(FULL, bi, off);
            if (ov > bv || (ov == bv && oi < bi)) { bv = ov; bi = oi; }
        }
        topv[it] = bv;
        topi[it] = bi;
        if ((bi >> 3) == lane) ms[bi & 7] = -1.0f;
    }

    float denom = 0.f;
#pragma unroll
    for (int it = 0; it < 8; ++it) denom += topv[it];
    denom = fmaxf(denom, 1e-12f);

    if (lane < 8) {
        outW[(size_t)warp * 8 + lane] = __fdiv_rn(topv[lane], denom);
        outI[(size_t)warp * 8 + lane] = (float)topi[lane];
    }
}

extern "C" void kernel_launch(void* const* d_in, const int* in_sizes, int n_in,
                              void* d_out, int out_size) {
    const float* H = (const float*)d_in[0];   // [T, 7168] fp32
    const float* W = (const float*)d_in[1];   // [256, 7168] fp32
    float* out = (float*)d_out;

    int T = in_sizes[0] / K_DIM;

    // output layout: [T*8 weights][T*8 indices][T*256 logits]
    float* outW = out;
    float* outI = out + (size_t)T * 8;
    float* logits = out + (size_t)T * 16;

    dim3 grid(T / BM, E_DIM / BN);
    moe_gemm_kernel<<<grid, 512>>>(H, W, logits, T);

    int warps = T;
    int threads = 256;
    int blocks = (warps * 32 + threads - 1) / threads;
    moe_router_kernel<<<blocks, threads>>>(logits, outW, outI, T);
}

// round 16
// speedup vs baseline: 2.0604x; 1.4337x over previous
#include <cuda_runtime.h>

#define K_DIM 7168
#define E_DIM 256
#define BM 128
#define BN 128
#define BK 32
#define KC_TILES 10   // Eigen kc=320 floats = 10 tiles of BK=32

// packed f32x2 FMA (Blackwell): per-component IEEE rn fma
__device__ __forceinline__ unsigned long long ffma2(unsigned long long a,
                                                    unsigned long long b,
                                                    unsigned long long c) {
    unsigned long long d;
    asm("fma.rn.f32x2 %0, %1, %2, %3;" : "=l"(d) : "l"(a), "l"(b), "l"(c));
    return d;
}

__device__ __forceinline__ unsigned long long fadd2(unsigned long long a,
                                                    unsigned long long b) {
    unsigned long long d;
    asm("add.rn.f32x2 %0, %1, %2;" : "=l"(d) : "l"(a), "l"(b));
    return d;
}

__device__ __forceinline__ unsigned long long dup_f32(float a) {
    unsigned long long p;
    asm("mov.b64 %0, {%1, %1};" : "=l"(p) : "r"(__float_as_uint(a)));
    return p;
}

// C[t, e] = sum_k A[t,k] * W[e,k] — fp32, Eigen-blocked accumulation order:
// c = ((0 + S_0) + S_1) + ... ; S_b = ascending-k fma partial over kc=320 block
// (last block = 128). BIT-EXACT match to XLA:CPU Eigen gemm — do not reorder.
//
// R8 skeleton (512 threads, 128x128 tile, natural smem layout, float4 loaders)
// with two overhead-only changes:
//  * accumulators packed along M: A loads as natural packed pairs (2 broadcast
//    LDS.128), only B's 4 scalars are duplicated -> 4 dups/thread-k (was 8),
//    issue slots per warp-k 27 -> 23.
//  * BK=32: 224 barriers instead of 448.
__global__ __launch_bounds__(512)
void moe_gemm_kernel(const float* __restrict__ A,
                     const float* __restrict__ W,
                     float* __restrict__ C, int T) {
    __shared__ float As[2][BK][BM];
    __shared__ float Bs[2][BK][BN];

    const int tid = threadIdx.x;
    const int tx = tid & 31;   // expert direction: 4 experts per thread
    const int ty = tid >> 5;   // token direction:  8 tokens per thread (warp id)
    const int m0 = blockIdx.x * BM;
    const int n0 = blockIdx.y * BN;

    // loader: 4 threads per row, 8 floats (2x float4) each (128 rows x 32 k)
    const int lr = tid >> 2;          // row 0..127
    const int lc = (tid & 3) * 8;     // K offset 0,8,16,24

    const float* Abase = A + (size_t)(m0 + lr) * K_DIM + lc;
    const float* Wbase = W + (size_t)(n0 + lr) * K_DIM + lc;

    // acc[n][p]: expert n0+tx*4+n, m-pair (m0+ty*8+2p, +2p+1)
    unsigned long long acc[4][4], bac[4][4];
#pragma unroll
    for (int n = 0; n < 4; ++n)
#pragma unroll
        for (int p = 0; p < 4; ++p) { acc[n][p] = 0ull; bac[n][p] = 0ull; }

    float4 aP0 = *reinterpret_cast<const float4*>(Abase);
    float4 aP1 = *reinterpret_cast<const float4*>(Abase + 4);
    float4 bP0 = *reinterpret_cast<const float4*>(Wbase);
    float4 bP1 = *reinterpret_cast<const float4*>(Wbase + 4);

    const int nIter = K_DIM / BK;  // 224
    for (int kt = 0; kt < nIter; ++kt) {
        const int buf = kt & 1;
        As[buf][lc + 0][lr] = aP0.x; As[buf][lc + 1][lr] = aP0.y;
        As[buf][lc + 2][lr] = aP0.z; As[buf][lc + 3][lr] = aP0.w;
        As[buf][lc + 4][lr] = aP1.x; As[buf][lc + 5][lr] = aP1.y;
        As[buf][lc + 6][lr] = aP1.z; As[buf][lc + 7][lr] = aP1.w;
        Bs[buf][lc + 0][lr] = bP0.x; Bs[buf][lc + 1][lr] = bP0.y;
        Bs[buf][lc + 2][lr] = bP0.z; Bs[buf][lc + 3][lr] = bP0.w;
        Bs[buf][lc + 4][lr] = bP1.x; Bs[buf][lc + 5][lr] = bP1.y;
        Bs[buf][lc + 6][lr] = bP1.z; Bs[buf][lc + 7][lr] = bP1.w;
        __syncthreads();

        // prefetch next tile from global (hidden under compute below)
        if (kt + 1 < nIter) {
            const float* an = Abase + (size_t)(kt + 1) * BK;
            const float* wn = Wbase + (size_t)(kt + 1) * BK;
            aP0 = *reinterpret_cast<const float4*>(an);
            aP1 = *reinterpret_cast<const float4*>(an + 4);
            bP0 = *reinterpret_cast<const float4*>(wn);
            bP1 = *reinterpret_cast<const float4*>(wn + 4);
        }

#pragma unroll
        for (int k = 0; k < BK; ++k) {
            // A: 8 consecutive m-floats = 4 NATURAL packed pairs,
            //    2 broadcast LDS.128 (lane-invariant address)
            ulonglong2 q01 = *reinterpret_cast<const ulonglong2*>(&As[buf][k][ty * 8]);
            ulonglong2 q23 = *reinterpret_cast<const ulonglong2*>(&As[buf][k][ty * 8 + 4]);
            // B: 4 expert scalars, 1 LDS.128, 4 dups (was 8 in R8)
            float4 bf = *reinterpret_cast<const float4*>(&Bs[buf][k][tx * 4]);
            unsigned long long pb0 = dup_f32(bf.x);
            unsigned long long pb1 = dup_f32(bf.y);
            unsigned long long pb2 = dup_f32(bf.z);
            unsigned long long pb3 = dup_f32(bf.w);
            bac[0][0] = ffma2(q01.x, pb0, bac[0][0]);
            bac[0][1] = ffma2(q01.y, pb0, bac[0][1]);
            bac[0][2] = ffma2(q23.x, pb0, bac[0][2]);
            bac[0][3] = ffma2(q23.y, pb0, bac[0][3]);
            bac[1][0] = ffma2(q01.x, pb1, bac[1][0]);
            bac[1][1] = ffma2(q01.y, pb1, bac[1][1]);
            bac[1][2] = ffma2(q23.x, pb1, bac[1][2]);
            bac[1][3] = ffma2(q23.y, pb1, bac[1][3]);
            bac[2][0] = ffma2(q01.x, pb2, bac[2][0]);
            bac[2][1] = ffma2(q01.y, pb2, bac[2][1]);
            bac[2][2] = ffma2(q23.x, pb2, bac[2][2]);
            bac[2][3] = ffma2(q23.y, pb2, bac[2][3]);
            bac[3][0] = ffma2(q01.x, pb3, bac[3][0]);
            bac[3][1] = ffma2(q01.y, pb3, bac[3][1]);
            bac[3][2] = ffma2(q23.x, pb3, bac[3][2]);
            bac[3][3] = ffma2(q23.y, pb3, bac[3][3]);
        }

        // Eigen kc=320 block boundary: c += S_b; S_b = 0
        if (((kt + 1) % KC_TILES) == 0) {
#pragma unroll
            for (int n = 0; n < 4; ++n)
#pragma unroll
                for (int p = 0; p < 4; ++p) {
                    acc[n][p] = fadd2(acc[n][p], bac[n][p]);
                    bac[n][p] = 0ull;
                }
        }
    }

    // final (remainder 128-wide) block flush
#pragma unroll
    for (int n = 0; n < 4; ++n)
#pragma unroll
        for (int p = 0; p < 4; ++p)
            acc[n][p] = fadd2(acc[n][p], bac[n][p]);

    // epilogue: component c of acc[n][p] -> C[m0+ty*8+2p+c][n0+tx*4+n]
#pragma unroll
    for (int p = 0; p < 4; ++p) {
        float2 e0 = *reinterpret_cast<float2*>(&acc[0][p]);
        float2 e1 = *reinterpret_cast<float2*>(&acc[1][p]);
        float2 e2 = *reinterpret_cast<float2*>(&acc[2][p]);
        float2 e3 = *reinterpret_cast<float2*>(&acc[3][p]);
        int mb = m0 + ty * 8 + p * 2;
        float* c0 = C + (size_t)mb * E_DIM + n0 + tx * 4;
        float* c1 = C + (size_t)(mb + 1) * E_DIM + n0 + tx * 4;
        *reinterpret_cast<float4*>(c0) = make_float4(e0.x, e1.x, e2.x, e3.x);
        *reinterpret_cast<float4*>(c1) = make_float4(e0.y, e1.y, e2.y, e3.y);
    }
}

// XLA EmitFastTanh replica — UNFUSED mul/add Horner (CPU LLVM does not
// contract), IEEE fdiv, clamp +-7.90531110763549805, |x|<0.0004 -> x.
__device__ __forceinline__ float xla_tanhf_nofma(float x) {
    float xc = fminf(fmaxf(x, -7.90531110763549805f), 7.90531110763549805f);
    float x2 = __fmul_rn(xc, xc);
    float np = -2.76076847742355e-16f;
    np = __fadd_rn(__fmul_rn(x2, np),  2.00018790482477e-13f);
    np = __fadd_rn(__fmul_rn(x2, np), -8.60467152213735e-11f);
    np = __fadd_rn(__fmul_rn(x2, np),  5.12229709037114e-08f);
    np = __fadd_rn(__fmul_rn(x2, np),  1.48572235717979e-05f);
    np = __fadd_rn(__fmul_rn(x2, np),  6.37261928875436e-04f);
    np = __fadd_rn(__fmul_rn(x2, np),  4.89352455891786e-03f);
    float num = __fmul_rn(xc, np);
    float dp = 1.19825839466702e-06f;
    dp = __fadd_rn(__fmul_rn(x2, dp), 1.18534705686654e-04f);
    dp = __fadd_rn(__fmul_rn(x2, dp), 2.26843463243900e-03f);
    dp = __fadd_rn(__fmul_rn(x2, dp), 4.89352518554385e-03f);
    float r = __fdiv_rn(num, dp);
    return (fabsf(x) < 0.0004f) ? x : r;
}

// XLA logistic: 0.5 + 0.5 * tanh(0.5 * x), unfused.
__device__ __forceinline__ float sigmoid_xla(float x) {
    float t = xla_tanhf_nofma(__fmul_rn(0.5f, x));
    return __fadd_rn(0.5f, __fmul_rn(0.5f, t));
}

// one warp per token
__global__ void moe_router_kernel(const float* __restrict__ logits,
                                  float* __restrict__ outW,
                                  float* __restrict__ outI, int T) {
    const unsigned FULL = 0xFFFFFFFFu;
    int warp = (blockIdx.x * blockDim.x + threadIdx.x) >> 5;
    int lane = threadIdx.x & 31;
    if (warp >= T) return;

    const float* row = logits + (size_t)warp * E_DIM;
    float4 v0 = *reinterpret_cast<const float4*>(row + lane * 8);
    float4 v1 = *reinterpret_cast<const float4*>(row + lane * 8 + 4);

    float s[8];
    s[0] = sigmoid_xla(v0.x); s[1] = sigmoid_xla(v0.y);
    s[2] = sigmoid_xla(v0.z); s[3] = sigmoid_xla(v0.w);
    s[4] = sigmoid_xla(v1.x); s[5] = sigmoid_xla(v1.y);
    s[6] = sigmoid_xla(v1.z); s[7] = sigmoid_xla(v1.w);

    // group sum over 32 experts (butterfly tree)
    float f[8];
#pragma unroll
    for (int j = 0; j < 8; ++j)
        f[j] = s[j] + __shfl_xor_sync(FULL, s[j], 2);
    float g[8];
#pragma unroll
    for (int j = 0; j < 8; ++j)
        g[j] = f[j] + __shfl_xor_sync(FULL, f[j], 1);
    float h0 = g[0] + g[4];
    float h1 = g[1] + g[5];
    float h2 = g[2] + g[6];
    float h3 = g[3] + g[7];
    float p0 = h0 + h2;
    float p1 = h1 + h3;
    float mygs = p0 + p1;     // group sum for group (lane>>2)
    int myg = lane >> 2;

    // rank of my group among 8 groups (ties -> lower index, jax top_k)
    int rank = 0;
#pragma unroll
    for (int h = 0; h < 8; ++h) {
        float gh = __shfl_sync(FULL, mygs, h * 4);
        if (h != myg && (gh > mygs || (gh == mygs && h < myg))) rank++;
    }
    bool sel = (rank < 4);

    float ms[8];
#pragma unroll
    for (int j = 0; j < 8; ++j) ms[j] = sel ? s[j] : 0.0f;

    float topv[8];
    int topi[8];
#pragma unroll
    for (int it = 0; it < 8; ++it) {
        float bv = -1.0f;
        int bi = 0;
#pragma unroll
        for (int j = 0; j < 8; ++j) {
            if (ms[j] > bv) { bv = ms[j]; bi = lane * 8 + j; }
        }
#pragma unroll
        for (int off = 16; off; off >>= 1) {
            float ov = __shfl_xor_sync(FULL, bv, off);
            int oi = __shfl_xor_sync(FULL, bi, off);
            if (ov > bv || (ov == bv && oi < bi)) { bv = ov; bi = oi; }
        }
        topv[it] = bv;
        topi[it] = bi;
        if ((bi >> 3) == lane) ms[bi & 7] = -1.0f;
    }

    float denom = 0.f;
#pragma unroll
    for (int it = 0; it < 8; ++it) denom += topv[it];
    denom = fmaxf(denom, 1e-12f);

    if (lane < 8) {
        outW[(size_t)warp * 8 + lane] = __fdiv_rn(topv[lane], denom);
        outI[(size_t)warp * 8 + lane] = (float)topi[lane];
    }
}

extern "C" void kernel_launch(void* const* d_in, const int* in_sizes, int n_in,
                              void* d_out, int out_size) {
    const float* H = (const float*)d_in[0];   // [T, 7168] fp32
    const float* W = (const float*)d_in[1];   // [256, 7168] fp32
    float* out = (float*)d_out;

    int T = in_sizes[0] / K_DIM;

    // output layout: [T*8 weights][T*8 indices][T*256 logits]
    float* outW = out;
    float* outI = out + (size_t)T * 8;
    float* logits = out + (size_t)T * 16;

    dim3 grid(T / BM, E_DIM / BN);
    moe_gemm_kernel<<<grid, 512>>>(H, W, logits, T);

    int warps = T;
    int threads = 256;
    int blocks = (warps * 32 + threads - 1) / threads;
    moe_router_kernel<<<blocks, threads>>>(logits, outW, outI, T);
}